// round 16
// baseline (speedup 1.0000x reference)
#include <cuda_runtime.h>
#include <cuda_fp16.h>

#define BB 8
#define TT 512
#define DD 64
#define TILE 32
#define NT (TT / TILE)               // 16 tiles per dim
#define NPAIR (NT * (NT + 1) / 2)    // 136 upper-tri tile pairs

#define SQRT_LOG2E 1.2011224087864498f
#define SGN2 0x80008000u

typedef unsigned long long u64;
typedef __half2 h2;

// ---- f16x2 helpers ---------------------------------------------------------
__device__ __forceinline__ h2 u2h(unsigned u) { return *(h2*)&u; }
__device__ __forceinline__ unsigned h2u(h2 h) { return *(unsigned*)&h; }
__device__ __forceinline__ h2 ex2negsq(h2 dif) {
    h2 m = __hmul2(__hneg2(dif), dif);
    unsigned r, u = *(unsigned*)&m;
    asm("ex2.approx.f16x2 %0, %1;" : "=r"(r) : "r"(u));
    return *(h2*)&r;
}

// ---- HMMA helpers (fragment mapping validated in R15) -----------------------
__device__ __forceinline__ void mma16816(float4& d,
    unsigned a0, unsigned a1, unsigned a2, unsigned a3,
    unsigned b0, unsigned b1) {
    asm("mma.sync.aligned.m16n8k16.row.col.f32.f16.f16.f32 "
        "{%0,%1,%2,%3}, {%4,%5,%6,%7}, {%8,%9}, {%0,%1,%2,%3};"
        : "+f"(d.x), "+f"(d.y), "+f"(d.z), "+f"(d.w)
        : "r"(a0), "r"(a1), "r"(a2), "r"(a3), "r"(b0), "r"(b1));
}
// Markidis split: f32 pair -> f16 hi + f16 residual
__device__ __forceinline__ void split2(float2 w, unsigned& hi, unsigned& lo) {
    h2 h = __floats2half2_rn(w.x, w.y);
    float2 bk = __half22float2(h);
    h2 l = __floats2half2_rn(w.x - bk.x, w.y - bk.y);
    hi = *(unsigned*)&h;
    lo = *(unsigned*)&l;
}

// ---------------------------------------------------------------------------
// SINGLE FUSED KERNEL.
// Phase 1: stage XI (= half(s*x_i), linear) and NXJ (= half(-s*x_j), XOR-
//          swizzled) straight from gmem x.
// Phase 2: per-block 64x64x64 GEMM v = x*W^T + b on the (idle) tensor pipe,
//          3-mma split precision (f32-accurate); warps write v as h2 into
//          VI (linear) / VJ (swizzled) smem.
// Phase 3: R12's d-packed f16x2 RBF hot loop (MUFU-roofline-bound), with
//          symmetric (i,j) outputs.
// ---------------------------------------------------------------------------
#define OFF_VI  2048     // half-unit offsets inside Sh
#define OFF_NXJ 4096
#define OFF_VJ  6144

__global__ __launch_bounds__(256, 4)
void rbf_fused_kernel(const float* __restrict__ x, const float* __restrict__ W,
                      const float* __restrict__ bias, float* __restrict__ out) {
    __shared__ __align__(16) __half Sh[8192];   // 16 KB: XI | VI | NXJ | VJ
    unsigned* S32 = (unsigned*)Sh;

    int b = blockIdx.y;
    int p = blockIdx.x;
    int ti = 0, rem = p;
    while (rem >= NT - ti) { rem -= NT - ti; ti++; }
    int tj = ti + rem;
    int i0 = ti * TILE, j0 = tj * TILE;

    int tid = threadIdx.x;

    // ---- Phase 1: XI / NXJ staging from gmem f32 ----
    {
        int r = tid >> 3, q0 = (tid & 7) * 4;    // row, h2-word base (4 words)
        const float* xi = x + (size_t)(b * TT + i0 + r) * DD + 2 * q0;
        const float* xj = x + (size_t)(b * TT + j0 + r) * DD + 2 * q0;
        float4 a0 = *(const float4*)xi;
        float4 a1 = *(const float4*)(xi + 4);
        float4 c0 = *(const float4*)xj;
        float4 c1 = *(const float4*)(xj + 4);

        unsigned w0 = h2u(__floats2half2_rn(SQRT_LOG2E * a0.x, SQRT_LOG2E * a0.y));
        unsigned w1 = h2u(__floats2half2_rn(SQRT_LOG2E * a0.z, SQRT_LOG2E * a0.w));
        unsigned w2 = h2u(__floats2half2_rn(SQRT_LOG2E * a1.x, SQRT_LOG2E * a1.y));
        unsigned w3 = h2u(__floats2half2_rn(SQRT_LOG2E * a1.z, SQRT_LOG2E * a1.w));
        *(uint2*)&S32[r * 32 + q0]     = make_uint2(w0, w1);
        *(uint2*)&S32[r * 32 + q0 + 2] = make_uint2(w2, w3);

        unsigned n0 = h2u(__floats2half2_rn(-SQRT_LOG2E * c0.x, -SQRT_LOG2E * c0.y));
        unsigned n1 = h2u(__floats2half2_rn(-SQRT_LOG2E * c0.z, -SQRT_LOG2E * c0.w));
        unsigned n2 = h2u(__floats2half2_rn(-SQRT_LOG2E * c1.x, -SQRT_LOG2E * c1.y));
        unsigned n3 = h2u(__floats2half2_rn(-SQRT_LOG2E * c1.z, -SQRT_LOG2E * c1.w));
        int msk = r & 15;
        int u0 = (q0 >> 1) ^ msk;
        int u1 = u0 ^ 1;
        *(uint2*)&S32[(OFF_NXJ >> 1) + r * 32 + 2 * u0] = make_uint2(n0, n1);
        *(uint2*)&S32[(OFF_NXJ >> 1) + r * 32 + 2 * u1] = make_uint2(n2, n3);
    }

    // ---- Phase 2: v for the 64 needed rows via split-precision HMMA ----
    {
        int lane = tid & 31, w = tid >> 5;
        int g = lane >> 2, tq = lane & 3;
        int mt = w >> 1, nh = w & 1;             // m-tile 0..3, n-half 0..1
        bool isI = (mt < 2);
        int lrbase = isI ? 16 * mt : 16 * (mt - 2);
        int rowbase = b * TT + (isI ? (i0 + lrbase) : (j0 + lrbase));

        // A fragments (x rows), hi + lo, 4 k-steps of 16
        unsigned ah[4][4], al[4][4];
#pragma unroll
        for (int ks = 0; ks < 4; ks++) {
            const float* p0 = x + (size_t)(rowbase + g) * DD + 16 * ks + 2 * tq;
            const float* p1 = p0 + 8 * DD;
            split2(*(const float2*)p0,       ah[ks][0], al[ks][0]);
            split2(*(const float2*)p1,       ah[ks][1], al[ks][1]);
            split2(*(const float2*)(p0 + 8), ah[ks][2], al[ks][2]);
            split2(*(const float2*)(p1 + 8), ah[ks][3], al[ks][3]);
        }

#pragma unroll
        for (int t = 0; t < 4; t++) {
            int nt = 4 * nh + t;
            float4 acc = make_float4(0.f, 0.f, 0.f, 0.f);
            int e = 8 * nt + g;                  // W row -> B fragment
#pragma unroll
            for (int ks = 0; ks < 4; ks++) {
                unsigned bh0, bl0, bh1, bl1;
                split2(*(const float2*)&W[e * DD + 16 * ks + 2 * tq],     bh0, bl0);
                split2(*(const float2*)&W[e * DD + 16 * ks + 2 * tq + 8], bh1, bl1);
                mma16816(acc, ah[ks][0], ah[ks][1], ah[ks][2], ah[ks][3], bh0, bh1);
                mma16816(acc, al[ks][0], al[ks][1], al[ks][2], al[ks][3], bh0, bh1);
                mma16816(acc, ah[ks][0], ah[ks][1], ah[ks][2], ah[ks][3], bl0, bl1);
            }
            int e0 = 8 * nt + 2 * tq;
            float2 bb = *(const float2*)&bias[e0];
            unsigned v0 = h2u(__floats2half2_rn(acc.x + bb.x, acc.y + bb.y)); // row lr
            unsigned v1 = h2u(__floats2half2_rn(acc.z + bb.x, acc.w + bb.y)); // row lr+8
            int qw = 4 * nt + tq;
            int lr0 = lrbase + g, lr1 = lr0 + 8;
            if (isI) {
                S32[(OFF_VI >> 1) + lr0 * 32 + qw] = v0;
                S32[(OFF_VI >> 1) + lr1 * 32 + qw] = v1;
            } else {
                int u = qw >> 1, lb = qw & 1;
                S32[(OFF_VJ >> 1) + lr0 * 32 + 2 * (u ^ (lr0 & 15)) + lb] = v0;
                S32[(OFF_VJ >> 1) + lr1 * 32 + 2 * (u ^ (lr1 & 15)) + lb] = v1;
            }
        }
    }
    __syncthreads();

    // ---- Phase 3: R12 hot loop (unchanged) ----
    int tx = tid & 15, ty = tid >> 4;
    const __half* pi = Sh + 2 * ty * 64;
    const __half* pj = Sh + OFF_NXJ + tx * 64;

    float denF[2][2], niF[2][2], njF[2][2];
#pragma unroll
    for (int r = 0; r < 2; r++)
#pragma unroll
        for (int c = 0; c < 2; c++) { denF[r][c] = 0.f; niF[r][c] = 0.f; njF[r][c] = 0.f; }

#pragma unroll
    for (int ch = 0; ch < 2; ch++) {         // 2 chunks of 32 d
        h2 dH[2][2], nH[2][2], qH[2][2];
        h2 z = __float2half2_rn(0.f);
#pragma unroll
        for (int r = 0; r < 2; r++)
#pragma unroll
            for (int c = 0; c < 2; c++) { dH[r][c] = z; nH[r][c] = z; qH[r][c] = z; }

#pragma unroll
        for (int s = 0; s < 8; s++) {        // 4 d's per step
            int u = ch * 8 + s;
            int uj = u ^ tx;

            uint2 fiA = *(const uint2*)(pi + 4 * u);
            uint2 fiB = *(const uint2*)(pi + 64 + 4 * u);
            uint2 fvA = *(const uint2*)(pi + OFF_VI + 4 * u);
            uint2 fvB = *(const uint2*)(pi + OFF_VI + 64 + 4 * u);
            uint2 njA = *(const uint2*)(pj + 4 * uj);
            uint2 njB = *(const uint2*)(pj + 1024 + 4 * uj);
            uint2 jvA = *(const uint2*)(pj + 2048 + 4 * uj);
            uint2 jvB = *(const uint2*)(pj + 2048 + 1024 + 4 * uj);

            h2 fi[2][2] = {{u2h(fiA.x), u2h(fiA.y)}, {u2h(fiB.x), u2h(fiB.y)}};
            h2 fv[2][2] = {{u2h(fvA.x), u2h(fvA.y)}, {u2h(fvB.x), u2h(fvB.y)}};
            h2 nj[2][2] = {{u2h(njA.x), u2h(njA.y)}, {u2h(njB.x), u2h(njB.y)}};
            h2 jv[2][2] = {{u2h(jvA.x), u2h(jvA.y)}, {u2h(jvB.x), u2h(jvB.y)}};

#pragma unroll
            for (int r = 0; r < 2; r++)
#pragma unroll
                for (int c = 0; c < 2; c++)
#pragma unroll
                    for (int s2 = 0; s2 < 2; s2++) {
                        h2 dif = __hadd2(fi[r][s2], nj[c][s2]);
                        h2 e   = ex2negsq(dif);
                        dH[r][c] = __hadd2(dH[r][c], e);
                        nH[r][c] = __hfma2(e, fv[r][s2], nH[r][c]);
                        qH[r][c] = __hfma2(e, jv[c][s2], qH[r][c]);
                    }
        }

#pragma unroll
        for (int r = 0; r < 2; r++)
#pragma unroll
            for (int c = 0; c < 2; c++) {
                float2 t;
                t = __half22float2(dH[r][c]); denF[r][c] += t.x + t.y;
                t = __half22float2(nH[r][c]); niF[r][c]  += t.x + t.y;
                t = __half22float2(qH[r][c]); njF[r][c]  += t.x + t.y;
            }
    }

    float* ob = out + (size_t)b * TT * TT;

#pragma unroll
    for (int r = 0; r < 2; r++) {
        int gi = i0 + 2 * ty + r;
#pragma unroll
        for (int c = 0; c < 2; c++) {
            int gj = j0 + tx + 16 * c;
            float rc;
            asm("rcp.approx.ftz.f32 %0, %1;" : "=f"(rc) : "f"(denF[r][c]));
            ob[(size_t)gi * TT + gj] = niF[r][c] * rc;
            if (ti != tj)
                ob[(size_t)gj * TT + gi] = njF[r][c] * rc;
        }
    }
}

extern "C" void kernel_launch(void* const* d_in, const int* in_sizes, int n_in,
                              void* d_out, int out_size) {
    const float* x = (const float*)d_in[0];    // (8,512,64)
    const float* W = (const float*)d_in[1];    // (64,64)
    const float* bias = (const float*)d_in[2]; // (64,)
    float* out = (float*)d_out;                // (8,512,512)

    rbf_fused_kernel<<<dim3(NPAIR, BB), 256>>>(x, W, bias, out);
}